// round 1
// baseline (speedup 1.0000x reference)
#include <cuda_runtime.h>
#include <cstdint>

// Problem constants
#define S 2048
#define D 1024
#define H 16
#define DI 64
#define DV 64
#define DFF 4096
#define SA_ELEMS ((size_t)H * S * S)   // 67108864

// -------------------- scratch (device globals; no allocation allowed) -----
__device__ float g_Wqkv[(size_t)D * 3 * D];      // packed [D, 3072]
__device__ float g_QKV[(size_t)S * 3 * D];       // [S, 3072]  (Q | K | V, each [S, H*64])
__device__ float g_Z[(size_t)S * D];             // [S, H*DV]
__device__ float g_ATT[(size_t)S * D];           // attention block output (residual for FF)
__device__ float g_H1[(size_t)S * DFF];          // FF hidden

// -------------------- pack WQ/WK/WV into one [D, 3072] B matrix -----------
__global__ void pack_w_kernel(const float* __restrict__ WQ,
                              const float* __restrict__ WK,
                              const float* __restrict__ WV) {
    int idx = blockIdx.x * 256 + threadIdx.x;
    if (idx >= D * 3 * D) return;
    int n = idx % (3 * D);
    int d = idx / (3 * D);
    int sect = n >> 10;           // 0=Q,1=K,2=V
    int nn = n & 1023;
    int h = nn >> 6, e = nn & 63;
    const float* W = (sect == 0) ? WQ : (sect == 1) ? WK : WV;
    g_Wqkv[idx] = W[((size_t)h * D + d) * 64 + e];
}

// -------------------- generic SGEMM: C = A[MxK] * B (+epilogue) -----------
// BTRANS=false: B is [K,N] row-major.  BTRANS=true: B is [N,K] row-major.
// EPI: 0 = none ; 1 = +bias[n] + res[m,n] ; 2 = relu(acc + bias[n])
template <bool BTRANS, int EPI>
__global__ __launch_bounds__(256)
void sgemm_kernel(const float* __restrict__ A, const float* __restrict__ B,
                  const float* __restrict__ bias, const float* __restrict__ res,
                  float* __restrict__ C, int M, int N, int K) {
    const int BM = 128, BN = 128, BK = 16;
    __shared__ float As[BK][BM];
    __shared__ float Bs[BK][BN];
    int tid = threadIdx.x;
    int bm = blockIdx.y * BM, bn = blockIdx.x * BN;
    int tx = tid & 15, ty = tid >> 4;

    float acc[8][8];
#pragma unroll
    for (int i = 0; i < 8; i++)
#pragma unroll
        for (int j = 0; j < 8; j++) acc[i][j] = 0.f;

    for (int k0 = 0; k0 < K; k0 += BK) {
        // A tile 128x16, vectorized along K, stored transposed As[k][m]
#pragma unroll
        for (int i = 0; i < 2; i++) {
            int id = tid + i * 256;
            int r = id >> 2, kk = (id & 3) * 4;
            float4 v = *(const float4*)(A + (size_t)(bm + r) * K + k0 + kk);
            As[kk + 0][r] = v.x; As[kk + 1][r] = v.y;
            As[kk + 2][r] = v.z; As[kk + 3][r] = v.w;
        }
        if (!BTRANS) {
#pragma unroll
            for (int i = 0; i < 2; i++) {
                int id = tid + i * 256;
                int r = id >> 5, c4 = (id & 31) * 4;
                float4 v = *(const float4*)(B + (size_t)(k0 + r) * N + bn + c4);
                *(float4*)&Bs[r][c4] = v;
            }
        } else {
#pragma unroll
            for (int i = 0; i < 2; i++) {
                int id = tid + i * 256;
                int r = id >> 2, kk = (id & 3) * 4;
                float4 v = *(const float4*)(B + (size_t)(bn + r) * K + k0 + kk);
                Bs[kk + 0][r] = v.x; Bs[kk + 1][r] = v.y;
                Bs[kk + 2][r] = v.z; Bs[kk + 3][r] = v.w;
            }
        }
        __syncthreads();
#pragma unroll
        for (int kk = 0; kk < BK; kk++) {
            float a[8], b[8];
#pragma unroll
            for (int i = 0; i < 8; i++) a[i] = As[kk][ty * 8 + i];
#pragma unroll
            for (int j = 0; j < 8; j++) b[j] = Bs[kk][tx * 8 + j];
#pragma unroll
            for (int i = 0; i < 8; i++)
#pragma unroll
                for (int j = 0; j < 8; j++) acc[i][j] += a[i] * b[j];
        }
        __syncthreads();
    }

#pragma unroll
    for (int i = 0; i < 8; i++) {
        int r = bm + ty * 8 + i;
#pragma unroll
        for (int j = 0; j < 8; j += 4) {
            int c = bn + tx * 8 + j;
            float4 v = make_float4(acc[i][j], acc[i][j + 1], acc[i][j + 2], acc[i][j + 3]);
            if (EPI >= 1) {
                v.x += bias[c]; v.y += bias[c + 1]; v.z += bias[c + 2]; v.w += bias[c + 3];
            }
            if (EPI == 1) {
                float4 rr = *(const float4*)(res + (size_t)r * N + c);
                v.x += rr.x; v.y += rr.y; v.z += rr.z; v.w += rr.w;
            }
            if (EPI == 2) {
                v.x = fmaxf(v.x, 0.f); v.y = fmaxf(v.y, 0.f);
                v.z = fmaxf(v.z, 0.f); v.w = fmaxf(v.w, 0.f);
            }
            *(float4*)(C + (size_t)r * N + c) = v;
        }
    }
}

// -------------------- scores: SA_pre[h,i,j] = Q.K^T*scale - (i-j)*slope ----
// Strictly-upper 64x64 tiles get zeros (== final softmax value there).
__global__ __launch_bounds__(256)
void scores_kernel(const float* __restrict__ QKV, float* __restrict__ SA) {
    int jt = blockIdx.x, it = blockIdx.y, h = blockIdx.z;
    int t = threadIdx.x;
    float* out = SA + ((size_t)h * S + (size_t)it * 64) * S + (size_t)jt * 64;

    if (jt > it) {  // strictly above diagonal: softmax prob == 0
#pragma unroll
        for (int r = 0; r < 4; r++) {
            int id = t + r * 256;
            int rr = id >> 4, c = (id & 15) * 4;
            *(float4*)(out + (size_t)rr * S + c) = make_float4(0.f, 0.f, 0.f, 0.f);
        }
        return;
    }

    __shared__ float Qs[64][65];  // [e][i]
    __shared__ float Ks[64][65];  // [e][j]
    const float* Qb = QKV + (size_t)(it * 64) * (3 * D) + h * 64;
    const float* Kb = QKV + (size_t)(jt * 64) * (3 * D) + D + h * 64;
#pragma unroll
    for (int r = 0; r < 4; r++) {
        int id = t + r * 256;
        int row = id >> 4, e4 = (id & 15) * 4;
        float4 q = *(const float4*)(Qb + (size_t)row * (3 * D) + e4);
        Qs[e4 + 0][row] = q.x; Qs[e4 + 1][row] = q.y;
        Qs[e4 + 2][row] = q.z; Qs[e4 + 3][row] = q.w;
        float4 k = *(const float4*)(Kb + (size_t)row * (3 * D) + e4);
        Ks[e4 + 0][row] = k.x; Ks[e4 + 1][row] = k.y;
        Ks[e4 + 2][row] = k.z; Ks[e4 + 3][row] = k.w;
    }
    __syncthreads();

    int tx = t & 15, ty = t >> 4;
    float acc[4][4];
#pragma unroll
    for (int i = 0; i < 4; i++)
#pragma unroll
        for (int j = 0; j < 4; j++) acc[i][j] = 0.f;
#pragma unroll
    for (int e = 0; e < 64; e++) {
        float a[4], b[4];
#pragma unroll
        for (int i = 0; i < 4; i++) a[i] = Qs[e][ty * 4 + i];
#pragma unroll
        for (int j = 0; j < 4; j++) b[j] = Ks[e][tx * 4 + j];
#pragma unroll
        for (int i = 0; i < 4; i++)
#pragma unroll
            for (int j = 0; j < 4; j++) acc[i][j] += a[i] * b[j];
    }

    float slope = exp2f(-0.5f * (float)(h + 1));
#pragma unroll
    for (int i = 0; i < 4; i++) {
        int gi = it * 64 + ty * 4 + i;
        float4 v;
        float vv[4];
#pragma unroll
        for (int j = 0; j < 4; j++) {
            int gj = jt * 64 + tx * 4 + j;
            vv[j] = (gj <= gi) ? (acc[i][j] * 0.125f - (float)(gi - gj) * slope) : 0.f;
        }
        v = make_float4(vv[0], vv[1], vv[2], vv[3]);
        *(float4*)(out + (size_t)(ty * 4 + i) * S + tx * 4) = v;
    }
}

// -------------------- in-place causal row softmax --------------------------
__global__ __launch_bounds__(256)
void softmax_kernel(float* __restrict__ SA) {
    int row = blockIdx.x;           // h*S + i
    int i = row & (S - 1);
    float* p = SA + (size_t)row * S;
    int t = threadIdx.x;
    __shared__ float red[8];

    float v[8];
    float mx = -1e30f;
#pragma unroll
    for (int r = 0; r < 8; r++) {
        int j = t + r * 256;
        float x = (j <= i) ? p[j] : -1e30f;
        v[r] = x;
        mx = fmaxf(mx, x);
    }
#pragma unroll
    for (int o = 16; o > 0; o >>= 1) mx = fmaxf(mx, __shfl_xor_sync(0xffffffffu, mx, o));
    if ((t & 31) == 0) red[t >> 5] = mx;
    __syncthreads();
    float bm = red[0];
#pragma unroll
    for (int w = 1; w < 8; w++) bm = fmaxf(bm, red[w]);
    __syncthreads();

    float sum = 0.f;
#pragma unroll
    for (int r = 0; r < 8; r++) {
        float e = __expf(v[r] - bm);   // j>i: exp(-huge) == 0
        v[r] = e;
        sum += e;
    }
#pragma unroll
    for (int o = 16; o > 0; o >>= 1) sum += __shfl_xor_sync(0xffffffffu, sum, o);
    if ((t & 31) == 0) red[t >> 5] = sum;
    __syncthreads();
    float bs = 0.f;
#pragma unroll
    for (int w = 0; w < 8; w++) bs += red[w];
    float inv = 1.f / bs;
#pragma unroll
    for (int r = 0; r < 8; r++) {
        int j = t + r * 256;
        if (j <= i) p[j] = v[r] * inv;
    }
}

// -------------------- z = SA @ V (lower triangle only) ---------------------
// Writes Z[s, h*64 + v]  (== zconcat layout)
__global__ __launch_bounds__(256)
void av_kernel(const float* __restrict__ SA, const float* __restrict__ QKV,
               float* __restrict__ Z) {
    int it = blockIdx.x, h = blockIdx.y;
    int t = threadIdx.x;
    int tx = t & 15, ty = t >> 4;
    __shared__ float SAs[64][65];  // [j][m]
    __shared__ float Vs[64][64];   // [j][v]

    const float* SAb = SA + ((size_t)h * S + (size_t)it * 64) * S;
    const float* Vb = QKV + 2 * D + (size_t)h * 64;

    float acc[4][4];
#pragma unroll
    for (int i = 0; i < 4; i++)
#pragma unroll
        for (int j = 0; j < 4; j++) acc[i][j] = 0.f;

    for (int kt = 0; kt <= it; kt++) {
#pragma unroll
        for (int r = 0; r < 4; r++) {
            int id = t + r * 256;
            int row = id >> 4, c4 = (id & 15) * 4;
            float4 a = *(const float4*)(SAb + (size_t)row * S + kt * 64 + c4);
            SAs[c4 + 0][row] = a.x; SAs[c4 + 1][row] = a.y;
            SAs[c4 + 2][row] = a.z; SAs[c4 + 3][row] = a.w;
            float4 vv = *(const float4*)(Vb + (size_t)(kt * 64 + row) * (3 * D) + c4);
            *(float4*)&Vs[row][c4] = vv;
        }
        __syncthreads();
#pragma unroll
        for (int kk = 0; kk < 64; kk++) {
            float a[4], b[4];
#pragma unroll
            for (int i = 0; i < 4; i++) a[i] = SAs[kk][ty * 4 + i];
#pragma unroll
            for (int j = 0; j < 4; j++) b[j] = Vs[kk][tx * 4 + j];
#pragma unroll
            for (int i = 0; i < 4; i++)
#pragma unroll
                for (int j = 0; j < 4; j++) acc[i][j] += a[i] * b[j];
        }
        __syncthreads();
    }
#pragma unroll
    for (int i = 0; i < 4; i++) {
        int s = it * 64 + ty * 4 + i;
        float4 v = make_float4(acc[i][0], acc[i][1], acc[i][2], acc[i][3]);
        *(float4*)(Z + (size_t)s * D + h * 64 + tx * 4) = v;
    }
}

// --------------------------- launch ---------------------------------------
extern "C" void kernel_launch(void* const* d_in, const int* in_sizes, int n_in,
                              void* d_out, int out_size) {
    const float* X    = (const float*)d_in[0];
    const float* WQ   = (const float*)d_in[1];
    const float* WK   = (const float*)d_in[2];
    const float* WV   = (const float*)d_in[3];
    const float* WOw  = (const float*)d_in[4];
    const float* WOb  = (const float*)d_in[5];
    const float* FF1w = (const float*)d_in[6];
    const float* FF1b = (const float*)d_in[7];
    const float* FF2w = (const float*)d_in[8];
    const float* FF2b = (const float*)d_in[9];

    float* SA  = (float*)d_out;
    float* OUT = (float*)d_out + SA_ELEMS;

    float *Wqkv, *QKV, *Z, *ATT, *H1;
    cudaGetSymbolAddress((void**)&Wqkv, g_Wqkv);
    cudaGetSymbolAddress((void**)&QKV, g_QKV);
    cudaGetSymbolAddress((void**)&Z, g_Z);
    cudaGetSymbolAddress((void**)&ATT, g_ATT);
    cudaGetSymbolAddress((void**)&H1, g_H1);

    // 1. pack QKV weights into [D, 3072]
    pack_w_kernel<<<(D * 3 * D + 255) / 256, 256>>>(WQ, WK, WV);

    // 2. QKV projection: [2048,1024] x [1024,3072]
    sgemm_kernel<false, 0><<<dim3(3 * D / 128, S / 128), 256>>>(
        X, Wqkv, nullptr, nullptr, QKV, S, 3 * D, D);

    // 3. scores (+ALiBi, causal) straight into the SA output region
    scores_kernel<<<dim3(S / 64, S / 64, H), 256>>>(QKV, SA);

    // 4. in-place softmax over causal prefix of each row
    softmax_kernel<<<H * S, 256>>>(SA);

    // 5. z = SA @ V  -> Z [S, H*DV]
    av_kernel<<<dim3(S / 64, H), 256>>>(SA, QKV, Z);

    // 6. attouts = X + Z @ WO_w^T + WO_b
    sgemm_kernel<true, 1><<<dim3(D / 128, S / 128), 256>>>(
        Z, WOw, WOb, X, ATT, S, D, D);

    // 7. H1 = relu(ATT @ FF1_w^T + FF1_b)
    sgemm_kernel<true, 2><<<dim3(DFF / 128, S / 128), 256>>>(
        ATT, FF1w, FF1b, nullptr, H1, S, DFF, D);

    // 8. out = ATT + H1 @ FF2_w^T + FF2_b
    sgemm_kernel<true, 1><<<dim3(D / 128, S / 128), 256>>>(
        H1, FF2w, FF2b, ATT, OUT, S, D, DFF);
}

// round 2
// speedup vs baseline: 1.7669x; 1.7669x over previous
#include <cuda_runtime.h>
#include <cstdint>

// Problem constants
#define S 2048
#define D 1024
#define H 16
#define DI 64
#define DV 64
#define DFF 4096
#define SA_ELEMS ((size_t)H * S * S)   // 67108864

// -------------------- scratch (device globals) -----------------------------
__device__ float g_WqkvT[(size_t)(3 * D) * D];   // packed transposed [3072, 1024]
__device__ float g_QKV[(size_t)S * 3 * D];       // [S, 3072]  (Q | K | V)
__device__ float g_Z[(size_t)S * D];             // [S, H*DV]
__device__ float g_ATT[(size_t)S * D];
__device__ float g_H1[(size_t)S * DFF];

// -------------------- helpers ---------------------------------------------
__device__ __forceinline__ unsigned f2tf32(float x) {
    unsigned u;
    asm("cvt.rna.tf32.f32 %0, %1;" : "=r"(u) : "f"(x));
    return u;
}

__device__ __forceinline__ void ldsm_x4(unsigned& r0, unsigned& r1, unsigned& r2, unsigned& r3,
                                        const float* p) {
    unsigned addr = (unsigned)__cvta_generic_to_shared(p);
    asm volatile("ldmatrix.sync.aligned.m8n8.x4.shared.b16 {%0,%1,%2,%3}, [%4];"
                 : "=r"(r0), "=r"(r1), "=r"(r2), "=r"(r3) : "r"(addr));
}

__device__ __forceinline__ void mma_tf32(float* c, const unsigned* a, const unsigned* b) {
    asm volatile(
        "mma.sync.aligned.m16n8k8.row.col.f32.tf32.tf32.f32 "
        "{%0,%1,%2,%3}, {%4,%5,%6,%7}, {%8,%9}, {%0,%1,%2,%3};"
        : "+f"(c[0]), "+f"(c[1]), "+f"(c[2]), "+f"(c[3])
        : "r"(a[0]), "r"(a[1]), "r"(a[2]), "r"(a[3]), "r"(b[0]), "r"(b[1]));
}

// -------------------- pack WQ/WK/WV transposed: [3072, 1024] ---------------
__global__ void pack_w_kernel(const float* __restrict__ WQ,
                              const float* __restrict__ WK,
                              const float* __restrict__ WV) {
    int idx = blockIdx.x * 256 + threadIdx.x;   // n*1024 + d
    if (idx >= 3 * D * D) return;
    int d = idx & 1023;
    int n = idx >> 10;
    int sect = n >> 10;
    int nn = n & 1023;
    int h = nn >> 6, e = nn & 63;
    const float* W = (sect == 0) ? WQ : (sect == 1) ? WK : WV;
    g_WqkvT[idx] = W[((size_t)h * D + d) * 64 + e];
}

// -------------------- tf32 tensor-core GEMM: C = A[MxK] * B[NxK]^T ---------
// EPI: 0 none ; 1 = +bias[n] + res[m,n] ; 2 = relu(acc + bias[n])
template <int EPI>
__global__ __launch_bounds__(256)
void tf32gemm_kernel(const float* __restrict__ A, const float* __restrict__ B,
                     const float* __restrict__ bias, const float* __restrict__ res,
                     float* __restrict__ C, int M, int N, int K) {
    const int BM = 128, BN = 128, BK = 16, LDS_ = 20;
    __shared__ float As[BM * LDS_];
    __shared__ float Bs[BN * LDS_];

    int tid = threadIdx.x;
    int lane = tid & 31, warp = tid >> 5;
    int warpM = warp >> 1, warpN = warp & 1;     // 4 x 2 warp grid
    int bm = blockIdx.y * BM, bn = blockIdx.x * BN;

    float acc[2][8][4];
#pragma unroll
    for (int i = 0; i < 2; i++)
#pragma unroll
        for (int j = 0; j < 8; j++)
#pragma unroll
            for (int r = 0; r < 4; r++) acc[i][j][r] = 0.f;

    // fragment-load base addresses (per k-step add col offset)
    int a_row = warpM * 32 + (lane & 15);
    int a_col = (lane >> 4) * 4;
    int b_row = warpN * 64 + (lane & 7) + ((lane >> 4) << 3);
    int b_col = ((lane >> 3) & 1) * 4;

    for (int k0 = 0; k0 < K; k0 += BK) {
        // load A,B tiles (each 128 rows x 16 floats), convert to tf32 bits
#pragma unroll
        for (int i = 0; i < 2; i++) {
            int id = tid + i * 256;
            int r = id >> 2, c4 = (id & 3) * 4;
            float4 va = *(const float4*)(A + (size_t)(bm + r) * K + k0 + c4);
            float4 vb = *(const float4*)(B + (size_t)(bn + r) * K + k0 + c4);
            float4 ta, tb;
            ta.x = __uint_as_float(f2tf32(va.x)); ta.y = __uint_as_float(f2tf32(va.y));
            ta.z = __uint_as_float(f2tf32(va.z)); ta.w = __uint_as_float(f2tf32(va.w));
            tb.x = __uint_as_float(f2tf32(vb.x)); tb.y = __uint_as_float(f2tf32(vb.y));
            tb.z = __uint_as_float(f2tf32(vb.z)); tb.w = __uint_as_float(f2tf32(vb.w));
            *(float4*)&As[r * LDS_ + c4] = ta;
            *(float4*)&Bs[r * LDS_ + c4] = tb;
        }
        __syncthreads();

#pragma unroll
        for (int ks = 0; ks < 2; ks++) {
            unsigned af[2][4];
            unsigned bf[8][2];
#pragma unroll
            for (int mt = 0; mt < 2; mt++) {
                ldsm_x4(af[mt][0], af[mt][1], af[mt][2], af[mt][3],
                        &As[(a_row + mt * 16) * LDS_ + ks * 8 + a_col]);
            }
#pragma unroll
            for (int np = 0; np < 4; np++) {
                ldsm_x4(bf[2 * np][0], bf[2 * np][1], bf[2 * np + 1][0], bf[2 * np + 1][1],
                        &Bs[(b_row + np * 16) * LDS_ + ks * 8 + b_col]);
            }
#pragma unroll
            for (int mt = 0; mt < 2; mt++)
#pragma unroll
                for (int nt = 0; nt < 8; nt++)
                    mma_tf32(acc[mt][nt], af[mt], bf[nt]);
        }
        __syncthreads();
    }

    // epilogue: thread t owns rows (g, g+8), cols (c*2, c*2+1) per tile
    int g = lane >> 2, c2 = (lane & 3) * 2;
#pragma unroll
    for (int mt = 0; mt < 2; mt++) {
#pragma unroll
        for (int half = 0; half < 2; half++) {
            int m = bm + warpM * 32 + mt * 16 + g + half * 8;
#pragma unroll
            for (int nt = 0; nt < 8; nt++) {
                int n = bn + warpN * 64 + nt * 8 + c2;
                float v0 = acc[mt][nt][half * 2 + 0];
                float v1 = acc[mt][nt][half * 2 + 1];
                if (EPI >= 1) { v0 += bias[n]; v1 += bias[n + 1]; }
                if (EPI == 1) {
                    float2 rr = *(const float2*)(res + (size_t)m * N + n);
                    v0 += rr.x; v1 += rr.y;
                }
                if (EPI == 2) { v0 = fmaxf(v0, 0.f); v1 = fmaxf(v1, 0.f); }
                float2 o; o.x = v0; o.y = v1;
                *(float2*)(C + (size_t)m * N + n) = o;
            }
        }
    }
}

// -------------------- scores: SA_pre[h,i,j] = Q.K^T*scale - (i-j)*slope ----
__global__ __launch_bounds__(256)
void scores_kernel(const float* __restrict__ QKV, float* __restrict__ SA) {
    int jt = blockIdx.x, it = blockIdx.y, h = blockIdx.z;
    int t = threadIdx.x;
    float* out = SA + ((size_t)h * S + (size_t)it * 64) * S + (size_t)jt * 64;

    if (jt > it) {
#pragma unroll
        for (int r = 0; r < 4; r++) {
            int id = t + r * 256;
            int rr = id >> 4, c = (id & 15) * 4;
            *(float4*)(out + (size_t)rr * S + c) = make_float4(0.f, 0.f, 0.f, 0.f);
        }
        return;
    }

    __shared__ float Qs[64][65];
    __shared__ float Ks[64][65];
    const float* Qb = QKV + (size_t)(it * 64) * (3 * D) + h * 64;
    const float* Kb = QKV + (size_t)(jt * 64) * (3 * D) + D + h * 64;
#pragma unroll
    for (int r = 0; r < 4; r++) {
        int id = t + r * 256;
        int row = id >> 4, e4 = (id & 15) * 4;
        float4 q = *(const float4*)(Qb + (size_t)row * (3 * D) + e4);
        Qs[e4 + 0][row] = q.x; Qs[e4 + 1][row] = q.y;
        Qs[e4 + 2][row] = q.z; Qs[e4 + 3][row] = q.w;
        float4 k = *(const float4*)(Kb + (size_t)row * (3 * D) + e4);
        Ks[e4 + 0][row] = k.x; Ks[e4 + 1][row] = k.y;
        Ks[e4 + 2][row] = k.z; Ks[e4 + 3][row] = k.w;
    }
    __syncthreads();

    int tx = t & 15, ty = t >> 4;
    float acc[4][4];
#pragma unroll
    for (int i = 0; i < 4; i++)
#pragma unroll
        for (int j = 0; j < 4; j++) acc[i][j] = 0.f;
#pragma unroll
    for (int e = 0; e < 64; e++) {
        float a[4], b[4];
#pragma unroll
        for (int i = 0; i < 4; i++) a[i] = Qs[e][ty * 4 + i];
#pragma unroll
        for (int j = 0; j < 4; j++) b[j] = Ks[e][tx * 4 + j];
#pragma unroll
        for (int i = 0; i < 4; i++)
#pragma unroll
            for (int j = 0; j < 4; j++) acc[i][j] += a[i] * b[j];
    }

    float slope = exp2f(-0.5f * (float)(h + 1));
#pragma unroll
    for (int i = 0; i < 4; i++) {
        int gi = it * 64 + ty * 4 + i;
        float vv[4];
#pragma unroll
        for (int j = 0; j < 4; j++) {
            int gj = jt * 64 + tx * 4 + j;
            vv[j] = (gj <= gi) ? (acc[i][j] * 0.125f - (float)(gi - gj) * slope) : 0.f;
        }
        *(float4*)(out + (size_t)(ty * 4 + i) * S + tx * 4) =
            make_float4(vv[0], vv[1], vv[2], vv[3]);
    }
}

// -------------------- in-place causal row softmax --------------------------
__global__ __launch_bounds__(256)
void softmax_kernel(float* __restrict__ SA) {
    int row = blockIdx.x;           // h*S + i
    int i = row & (S - 1);
    float* p = SA + (size_t)row * S;
    int t = threadIdx.x;
    __shared__ float red[8];

    float v[8];
    float mx = -1e30f;
#pragma unroll
    for (int r = 0; r < 8; r++) {
        int j = t + r * 256;
        float x = (j <= i) ? p[j] : -1e30f;
        v[r] = x;
        mx = fmaxf(mx, x);
    }
#pragma unroll
    for (int o = 16; o > 0; o >>= 1) mx = fmaxf(mx, __shfl_xor_sync(0xffffffffu, mx, o));
    if ((t & 31) == 0) red[t >> 5] = mx;
    __syncthreads();
    float bm = red[0];
#pragma unroll
    for (int w = 1; w < 8; w++) bm = fmaxf(bm, red[w]);
    __syncthreads();

    float sum = 0.f;
#pragma unroll
    for (int r = 0; r < 8; r++) {
        float e = __expf(v[r] - bm);
        v[r] = e;
        sum += e;
    }
#pragma unroll
    for (int o = 16; o > 0; o >>= 1) sum += __shfl_xor_sync(0xffffffffu, sum, o);
    if ((t & 31) == 0) red[t >> 5] = sum;
    __syncthreads();
    float bs = 0.f;
#pragma unroll
    for (int w = 0; w < 8; w++) bs += red[w];
    float inv = 1.f / bs;
#pragma unroll
    for (int r = 0; r < 8; r++) {
        int j = t + r * 256;
        if (j <= i) p[j] = v[r] * inv;
    }
}

// -------------------- z = SA @ V (lower triangle only) ---------------------
__global__ __launch_bounds__(256)
void av_kernel(const float* __restrict__ SA, const float* __restrict__ QKV,
               float* __restrict__ Z) {
    int it = blockIdx.x, h = blockIdx.y;
    int t = threadIdx.x;
    int tx = t & 15, ty = t >> 4;
    __shared__ float SAs[64][65];
    __shared__ float Vs[64][64];

    const float* SAb = SA + ((size_t)h * S + (size_t)it * 64) * S;
    const float* Vb = QKV + 2 * D + (size_t)h * 64;

    float acc[4][4];
#pragma unroll
    for (int i = 0; i < 4; i++)
#pragma unroll
        for (int j = 0; j < 4; j++) acc[i][j] = 0.f;

    for (int kt = 0; kt <= it; kt++) {
#pragma unroll
        for (int r = 0; r < 4; r++) {
            int id = t + r * 256;
            int row = id >> 4, c4 = (id & 15) * 4;
            float4 a = *(const float4*)(SAb + (size_t)row * S + kt * 64 + c4);
            SAs[c4 + 0][row] = a.x; SAs[c4 + 1][row] = a.y;
            SAs[c4 + 2][row] = a.z; SAs[c4 + 3][row] = a.w;
            float4 vv = *(const float4*)(Vb + (size_t)(kt * 64 + row) * (3 * D) + c4);
            *(float4*)&Vs[row][c4] = vv;
        }
        __syncthreads();
#pragma unroll
        for (int kk = 0; kk < 64; kk++) {
            float a[4], b[4];
#pragma unroll
            for (int i = 0; i < 4; i++) a[i] = SAs[kk][ty * 4 + i];
#pragma unroll
            for (int j = 0; j < 4; j++) b[j] = Vs[kk][tx * 4 + j];
#pragma unroll
            for (int i = 0; i < 4; i++)
#pragma unroll
                for (int j = 0; j < 4; j++) acc[i][j] += a[i] * b[j];
        }
        __syncthreads();
    }
#pragma unroll
    for (int i = 0; i < 4; i++) {
        int s = it * 64 + ty * 4 + i;
        *(float4*)(Z + (size_t)s * D + h * 64 + tx * 4) =
            make_float4(acc[i][0], acc[i][1], acc[i][2], acc[i][3]);
    }
}

// --------------------------- launch ---------------------------------------
extern "C" void kernel_launch(void* const* d_in, const int* in_sizes, int n_in,
                              void* d_out, int out_size) {
    const float* X    = (const float*)d_in[0];
    const float* WQ   = (const float*)d_in[1];
    const float* WK   = (const float*)d_in[2];
    const float* WV   = (const float*)d_in[3];
    const float* WOw  = (const float*)d_in[4];
    const float* WOb  = (const float*)d_in[5];
    const float* FF1w = (const float*)d_in[6];
    const float* FF1b = (const float*)d_in[7];
    const float* FF2w = (const float*)d_in[8];
    const float* FF2b = (const float*)d_in[9];

    float* SA  = (float*)d_out;
    float* OUT = (float*)d_out + SA_ELEMS;

    float *WqkvT, *QKV, *Z, *ATT, *H1;
    cudaGetSymbolAddress((void**)&WqkvT, g_WqkvT);
    cudaGetSymbolAddress((void**)&QKV, g_QKV);
    cudaGetSymbolAddress((void**)&Z, g_Z);
    cudaGetSymbolAddress((void**)&ATT, g_ATT);
    cudaGetSymbolAddress((void**)&H1, g_H1);

    // 1. pack QKV weights transposed into [3072, 1024]
    pack_w_kernel<<<(3 * D * D + 255) / 256, 256>>>(WQ, WK, WV);

    // 2. QKV projection: [2048,1024] x [3072,1024]^T  (tensor cores, tf32)
    tf32gemm_kernel<0><<<dim3(3 * D / 128, S / 128), 256>>>(
        X, WqkvT, nullptr, nullptr, QKV, S, 3 * D, D);

    // 3. scores (+ALiBi, causal) straight into SA output (fp32 anchor)
    scores_kernel<<<dim3(S / 64, S / 64, H), 256>>>(QKV, SA);

    // 4. in-place softmax over causal prefix of each row
    softmax_kernel<<<H * S, 256>>>(SA);

    // 5. z = SA @ V
    av_kernel<<<dim3(S / 64, H), 256>>>(SA, QKV, Z);

    // 6. attouts = X + Z @ WO_w^T + WO_b
    tf32gemm_kernel<1><<<dim3(D / 128, S / 128), 256>>>(
        Z, WOw, WOb, X, ATT, S, D, D);

    // 7. H1 = relu(ATT @ FF1_w^T + FF1_b)
    tf32gemm_kernel<2><<<dim3(DFF / 128, S / 128), 256>>>(
        ATT, FF1w, FF1b, nullptr, H1, S, DFF, D);

    // 8. out = ATT + H1 @ FF2_w^T + FF2_b
    tf32gemm_kernel<1><<<dim3(D / 128, S / 128), 256>>>(
        H1, FF2w, FF2b, ATT, OUT, S, D, DFF);
}

// round 3
// speedup vs baseline: 1.9204x; 1.0869x over previous
#include <cuda_runtime.h>
#include <cstdint>

// Problem constants
#define S 2048
#define D 1024
#define H 16
#define DI 64
#define DV 64
#define DFF 4096
#define SA_ELEMS ((size_t)H * S * S)   // 67108864

// -------------------- scratch (device globals) -----------------------------
__device__ float g_WqkvT[(size_t)(3 * D) * D];   // packed transposed [3072, 1024]
__device__ float g_QKV[(size_t)S * 3 * D];       // [S, 3072]  (Q | K | V)
__device__ float g_Z[(size_t)S * D];             // [S, H*DV]
__device__ float g_ATT[(size_t)S * D];
__device__ float g_H1[(size_t)S * DFF];

// -------------------- helpers ---------------------------------------------
__device__ __forceinline__ unsigned f2tf32(float x) {
    unsigned u;
    asm("cvt.rna.tf32.f32 %0, %1;" : "=r"(u) : "f"(x));
    return u;
}

__device__ __forceinline__ void ldsm_x4(unsigned& r0, unsigned& r1, unsigned& r2, unsigned& r3,
                                        const float* p) {
    unsigned addr = (unsigned)__cvta_generic_to_shared(p);
    asm volatile("ldmatrix.sync.aligned.m8n8.x4.shared.b16 {%0,%1,%2,%3}, [%4];"
                 : "=r"(r0), "=r"(r1), "=r"(r2), "=r"(r3) : "r"(addr));
}

__device__ __forceinline__ void mma_tf32(float* c, const unsigned* a, const unsigned* b) {
    asm volatile(
        "mma.sync.aligned.m16n8k8.row.col.f32.tf32.tf32.f32 "
        "{%0,%1,%2,%3}, {%4,%5,%6,%7}, {%8,%9}, {%0,%1,%2,%3};"
        : "+f"(c[0]), "+f"(c[1]), "+f"(c[2]), "+f"(c[3])
        : "r"(a[0]), "r"(a[1]), "r"(a[2]), "r"(a[3]), "r"(b[0]), "r"(b[1]));
}

// -------------------- pack WQ/WK/WV transposed: [3072, 1024] ---------------
__global__ void pack_w_kernel(const float* __restrict__ WQ,
                              const float* __restrict__ WK,
                              const float* __restrict__ WV) {
    int idx = blockIdx.x * 256 + threadIdx.x;   // n*1024 + d
    if (idx >= 3 * D * D) return;
    int d = idx & 1023;
    int n = idx >> 10;
    int sect = n >> 10;
    int nn = n & 1023;
    int h = nn >> 6, e = nn & 63;
    const float* W = (sect == 0) ? WQ : (sect == 1) ? WK : WV;
    g_WqkvT[idx] = W[((size_t)h * D + d) * 64 + e];
}

// -------------------- tf32 tensor-core GEMM: C = A[MxK] * B[NxK]^T ---------
// EPI: 0 none ; 1 = +bias[n] + res[m,n] ; 2 = relu(acc + bias[n])
template <int EPI>
__global__ __launch_bounds__(256)
void tf32gemm_kernel(const float* __restrict__ A, const float* __restrict__ B,
                     const float* __restrict__ bias, const float* __restrict__ res,
                     float* __restrict__ C, int M, int N, int K) {
    const int BM = 128, BN = 128, BK = 16, LDS_ = 20;
    __shared__ float As[BM * LDS_];
    __shared__ float Bs[BN * LDS_];

    int tid = threadIdx.x;
    int lane = tid & 31, warp = tid >> 5;
    int warpM = warp >> 1, warpN = warp & 1;     // 4 x 2 warp grid
    int bm = blockIdx.y * BM, bn = blockIdx.x * BN;

    float acc[2][8][4];
#pragma unroll
    for (int i = 0; i < 2; i++)
#pragma unroll
        for (int j = 0; j < 8; j++)
#pragma unroll
            for (int r = 0; r < 4; r++) acc[i][j][r] = 0.f;

    int a_row = warpM * 32 + (lane & 15);
    int a_col = (lane >> 4) * 4;
    int b_row = warpN * 64 + (lane & 7) + ((lane >> 4) << 3);
    int b_col = ((lane >> 3) & 1) * 4;

    for (int k0 = 0; k0 < K; k0 += BK) {
#pragma unroll
        for (int i = 0; i < 2; i++) {
            int id = tid + i * 256;
            int r = id >> 2, c4 = (id & 3) * 4;
            float4 va = *(const float4*)(A + (size_t)(bm + r) * K + k0 + c4);
            float4 vb = *(const float4*)(B + (size_t)(bn + r) * K + k0 + c4);
            float4 ta, tb;
            ta.x = __uint_as_float(f2tf32(va.x)); ta.y = __uint_as_float(f2tf32(va.y));
            ta.z = __uint_as_float(f2tf32(va.z)); ta.w = __uint_as_float(f2tf32(va.w));
            tb.x = __uint_as_float(f2tf32(vb.x)); tb.y = __uint_as_float(f2tf32(vb.y));
            tb.z = __uint_as_float(f2tf32(vb.z)); tb.w = __uint_as_float(f2tf32(vb.w));
            *(float4*)&As[r * LDS_ + c4] = ta;
            *(float4*)&Bs[r * LDS_ + c4] = tb;
        }
        __syncthreads();

#pragma unroll
        for (int ks = 0; ks < 2; ks++) {
            unsigned af[2][4];
            unsigned bf[8][2];
#pragma unroll
            for (int mt = 0; mt < 2; mt++) {
                ldsm_x4(af[mt][0], af[mt][1], af[mt][2], af[mt][3],
                        &As[(a_row + mt * 16) * LDS_ + ks * 8 + a_col]);
            }
#pragma unroll
            for (int np = 0; np < 4; np++) {
                ldsm_x4(bf[2 * np][0], bf[2 * np][1], bf[2 * np + 1][0], bf[2 * np + 1][1],
                        &Bs[(b_row + np * 16) * LDS_ + ks * 8 + b_col]);
            }
#pragma unroll
            for (int mt = 0; mt < 2; mt++)
#pragma unroll
                for (int nt = 0; nt < 8; nt++)
                    mma_tf32(acc[mt][nt], af[mt], bf[nt]);
        }
        __syncthreads();
    }

    int g = lane >> 2, c2 = (lane & 3) * 2;
#pragma unroll
    for (int mt = 0; mt < 2; mt++) {
#pragma unroll
        for (int half = 0; half < 2; half++) {
            int m = bm + warpM * 32 + mt * 16 + g + half * 8;
#pragma unroll
            for (int nt = 0; nt < 8; nt++) {
                int n = bn + warpN * 64 + nt * 8 + c2;
                float v0 = acc[mt][nt][half * 2 + 0];
                float v1 = acc[mt][nt][half * 2 + 1];
                if (EPI >= 1) { v0 += bias[n]; v1 += bias[n + 1]; }
                if (EPI == 1) {
                    float2 rr = *(const float2*)(res + (size_t)m * N + n);
                    v0 += rr.x; v1 += rr.y;
                }
                if (EPI == 2) { v0 = fmaxf(v0, 0.f); v1 = fmaxf(v1, 0.f); }
                float2 o; o.x = v0; o.y = v1;
                *(float2*)(C + (size_t)m * N + n) = o;
            }
        }
    }
}

// -------------------- scores (tensor cores, 3xTF32 for fp32 accuracy) ------
// SA_pre[h,i,j] = (Q.K^T)/8 - (i-j)*slope for j<=i else 0
// Block: 128(i) x 128(j), grid (16,16,16)
__global__ __launch_bounds__(256)
void scores_tc_kernel(const float* __restrict__ QKV, float* __restrict__ SA) {
    const int LDS_ = 20;
    int jt = blockIdx.x, it = blockIdx.y, h = blockIdx.z;
    int bm = it * 128, bn = jt * 128;
    float* out = SA + ((size_t)h * S + bm) * S + bn;
    int tid = threadIdx.x;

    if (jt > it) {   // strictly above diagonal at 128-granularity: zeros
#pragma unroll
        for (int r = 0; r < 16; r++) {
            int id = tid + r * 256;
            int row = id >> 5, c4 = (id & 31) * 4;
            *(float4*)(out + (size_t)row * S + c4) = make_float4(0.f, 0.f, 0.f, 0.f);
        }
        return;
    }

    __shared__ float Qh[128 * LDS_], Ql[128 * LDS_];
    __shared__ float Kh[128 * LDS_], Kl[128 * LDS_];

    int lane = tid & 31, warp = tid >> 5;
    int warpM = warp >> 1, warpN = warp & 1;

    float acc[2][8][4];
#pragma unroll
    for (int i = 0; i < 2; i++)
#pragma unroll
        for (int j = 0; j < 8; j++)
#pragma unroll
            for (int r = 0; r < 4; r++) acc[i][j][r] = 0.f;

    int a_row = warpM * 32 + (lane & 15);
    int a_col = (lane >> 4) * 4;
    int b_row = warpN * 64 + (lane & 7) + ((lane >> 4) << 3);
    int b_col = ((lane >> 3) & 1) * 4;

    const float* Qb = QKV + (size_t)bm * (3 * D) + h * 64;
    const float* Kb = QKV + (size_t)bn * (3 * D) + D + h * 64;

    for (int kc = 0; kc < 4; kc++) {   // 4 chunks of 16 over DI=64
#pragma unroll
        for (int i = 0; i < 2; i++) {
            int id = tid + i * 256;
            int row = id >> 2, c4 = (id & 3) * 4;
            float4 q = *(const float4*)(Qb + (size_t)row * (3 * D) + kc * 16 + c4);
            float4 k = *(const float4*)(Kb + (size_t)row * (3 * D) + kc * 16 + c4);
            float4 qh, ql, kh, kl;
            qh.x = __uint_as_float(f2tf32(q.x)); ql.x = __uint_as_float(f2tf32(q.x - qh.x));
            qh.y = __uint_as_float(f2tf32(q.y)); ql.y = __uint_as_float(f2tf32(q.y - qh.y));
            qh.z = __uint_as_float(f2tf32(q.z)); ql.z = __uint_as_float(f2tf32(q.z - qh.z));
            qh.w = __uint_as_float(f2tf32(q.w)); ql.w = __uint_as_float(f2tf32(q.w - qh.w));
            kh.x = __uint_as_float(f2tf32(k.x)); kl.x = __uint_as_float(f2tf32(k.x - kh.x));
            kh.y = __uint_as_float(f2tf32(k.y)); kl.y = __uint_as_float(f2tf32(k.y - kh.y));
            kh.z = __uint_as_float(f2tf32(k.z)); kl.z = __uint_as_float(f2tf32(k.z - kh.z));
            kh.w = __uint_as_float(f2tf32(k.w)); kl.w = __uint_as_float(f2tf32(k.w - kh.w));
            *(float4*)&Qh[row * LDS_ + c4] = qh;
            *(float4*)&Ql[row * LDS_ + c4] = ql;
            *(float4*)&Kh[row * LDS_ + c4] = kh;
            *(float4*)&Kl[row * LDS_ + c4] = kl;
        }
        __syncthreads();

#pragma unroll
        for (int ks = 0; ks < 2; ks++) {
            unsigned afh[2][4], afl[2][4];
            unsigned bfh[8][2], bfl[8][2];
#pragma unroll
            for (int mt = 0; mt < 2; mt++) {
                ldsm_x4(afh[mt][0], afh[mt][1], afh[mt][2], afh[mt][3],
                        &Qh[(a_row + mt * 16) * LDS_ + ks * 8 + a_col]);
                ldsm_x4(afl[mt][0], afl[mt][1], afl[mt][2], afl[mt][3],
                        &Ql[(a_row + mt * 16) * LDS_ + ks * 8 + a_col]);
            }
#pragma unroll
            for (int np = 0; np < 4; np++) {
                ldsm_x4(bfh[2 * np][0], bfh[2 * np][1], bfh[2 * np + 1][0], bfh[2 * np + 1][1],
                        &Kh[(b_row + np * 16) * LDS_ + ks * 8 + b_col]);
                ldsm_x4(bfl[2 * np][0], bfl[2 * np][1], bfl[2 * np + 1][0], bfl[2 * np + 1][1],
                        &Kl[(b_row + np * 16) * LDS_ + ks * 8 + b_col]);
            }
#pragma unroll
            for (int mt = 0; mt < 2; mt++)
#pragma unroll
                for (int nt = 0; nt < 8; nt++) {
                    mma_tf32(acc[mt][nt], afh[mt], bfh[nt]);
                    mma_tf32(acc[mt][nt], afh[mt], bfl[nt]);
                    mma_tf32(acc[mt][nt], afl[mt], bfh[nt]);
                }
        }
        __syncthreads();
    }

    float slope = exp2f(-0.5f * (float)(h + 1));
    int g = lane >> 2, c2 = (lane & 3) * 2;
#pragma unroll
    for (int mt = 0; mt < 2; mt++) {
#pragma unroll
        for (int half = 0; half < 2; half++) {
            int li = warpM * 32 + mt * 16 + g + half * 8;
            int gi = bm + li;
#pragma unroll
            for (int nt = 0; nt < 8; nt++) {
                int lj = warpN * 64 + nt * 8 + c2;
                int gj = bn + lj;
                float v0 = acc[mt][nt][half * 2 + 0];
                float v1 = acc[mt][nt][half * 2 + 1];
                v0 = (gj <= gi) ? (v0 * 0.125f - (float)(gi - gj) * slope) : 0.f;
                v1 = (gj + 1 <= gi) ? (v1 * 0.125f - (float)(gi - gj - 1) * slope) : 0.f;
                float2 o; o.x = v0; o.y = v1;
                *(float2*)(out + (size_t)li * S + lj) = o;
            }
        }
    }
}

// -------------------- in-place causal row softmax --------------------------
__global__ __launch_bounds__(256)
void softmax_kernel(float* __restrict__ SA) {
    int row = blockIdx.x;           // h*S + i
    int i = row & (S - 1);
    float* p = SA + (size_t)row * S;
    int t = threadIdx.x;
    __shared__ float red[8];

    float v[8];
    float mx = -1e30f;
#pragma unroll
    for (int r = 0; r < 8; r++) {
        int j = t + r * 256;
        float x = (j <= i) ? p[j] : -1e30f;
        v[r] = x;
        mx = fmaxf(mx, x);
    }
#pragma unroll
    for (int o = 16; o > 0; o >>= 1) mx = fmaxf(mx, __shfl_xor_sync(0xffffffffu, mx, o));
    if ((t & 31) == 0) red[t >> 5] = mx;
    __syncthreads();
    float bm = red[0];
#pragma unroll
    for (int w = 1; w < 8; w++) bm = fmaxf(bm, red[w]);
    __syncthreads();

    float sum = 0.f;
#pragma unroll
    for (int r = 0; r < 8; r++) {
        float e = __expf(v[r] - bm);
        v[r] = e;
        sum += e;
    }
#pragma unroll
    for (int o = 16; o > 0; o >>= 1) sum += __shfl_xor_sync(0xffffffffu, sum, o);
    if ((t & 31) == 0) red[t >> 5] = sum;
    __syncthreads();
    float bs = 0.f;
#pragma unroll
    for (int w = 0; w < 8; w++) bs += red[w];
    float inv = 1.f / bs;
#pragma unroll
    for (int r = 0; r < 8; r++) {
        int j = t + r * 256;
        if (j <= i) p[j] = v[r] * inv;
    }
}

// -------------------- z = SA @ V (tensor cores, tf32) ----------------------
// Block: 128 rows x 64 cols (one head). grid (16, 16) = (row-block, head)
__global__ __launch_bounds__(256)
void av_tc_kernel(const float* __restrict__ SA, const float* __restrict__ QKV,
                  float* __restrict__ Z) {
    const int LDS_ = 20;
    int bi = blockIdx.x, h = blockIdx.y;
    int bm = bi * 128;
    int tid = threadIdx.x;
    int lane = tid & 31, warp = tid >> 5;

    __shared__ float SAs[128 * LDS_];
    __shared__ float Vs[64 * LDS_];

    float acc[8][4];
#pragma unroll
    for (int j = 0; j < 8; j++)
#pragma unroll
        for (int r = 0; r < 4; r++) acc[j][r] = 0.f;

    int a_row = warp * 16 + (lane & 15);
    int a_col = (lane >> 4) * 4;
    int b_row = (lane & 7) + ((lane >> 4) << 3);
    int b_col = ((lane >> 3) & 1) * 4;

    const float* SAb = SA + ((size_t)h * S + bm) * S;
    const float* Vb = QKV + 2 * D + (size_t)h * 64;

    int nchunks = (bm + 128) / 16;   // need j <= bm+127
    for (int kc = 0; kc < nchunks; kc++) {
        int k0 = kc * 16;
        // SA chunk: 128 rows x 16 cols
#pragma unroll
        for (int i = 0; i < 2; i++) {
            int id = tid + i * 256;
            int row = id >> 2, c4 = (id & 3) * 4;
            float4 a = *(const float4*)(SAb + (size_t)row * S + k0 + c4);
            float4 ta;
            ta.x = __uint_as_float(f2tf32(a.x)); ta.y = __uint_as_float(f2tf32(a.y));
            ta.z = __uint_as_float(f2tf32(a.z)); ta.w = __uint_as_float(f2tf32(a.w));
            *(float4*)&SAs[row * LDS_ + c4] = ta;
        }
        // V chunk transposed: Vs[v][jloc], 16 j-rows x 64 v-cols
        {
            int jloc = tid >> 6, v = tid & 63;
#pragma unroll
            for (int i = 0; i < 4; i++) {
                int jj = jloc + i * 4;
                float x = Vb[(size_t)(k0 + jj) * (3 * D) + v];
                Vs[v * LDS_ + jj] = __uint_as_float(f2tf32(x));
            }
        }
        __syncthreads();

#pragma unroll
        for (int ks = 0; ks < 2; ks++) {
            unsigned af[4];
            unsigned bf[8][2];
            ldsm_x4(af[0], af[1], af[2], af[3],
                    &SAs[a_row * LDS_ + ks * 8 + a_col]);
#pragma unroll
            for (int np = 0; np < 4; np++) {
                ldsm_x4(bf[2 * np][0], bf[2 * np][1], bf[2 * np + 1][0], bf[2 * np + 1][1],
                        &Vs[(b_row + np * 16) * LDS_ + ks * 8 + b_col]);
            }
#pragma unroll
            for (int nt = 0; nt < 8; nt++)
                mma_tf32(acc[nt], af, bf[nt]);
        }
        __syncthreads();
    }

    int g = lane >> 2, c2 = (lane & 3) * 2;
#pragma unroll
    for (int half = 0; half < 2; half++) {
        int m = bm + warp * 16 + g + half * 8;
#pragma unroll
        for (int nt = 0; nt < 8; nt++) {
            int n = h * 64 + nt * 8 + c2;
            float2 o;
            o.x = acc[nt][half * 2 + 0];
            o.y = acc[nt][half * 2 + 1];
            *(float2*)(Z + (size_t)m * D + n) = o;
        }
    }
}

// --------------------------- launch ---------------------------------------
extern "C" void kernel_launch(void* const* d_in, const int* in_sizes, int n_in,
                              void* d_out, int out_size) {
    const float* X    = (const float*)d_in[0];
    const float* WQ   = (const float*)d_in[1];
    const float* WK   = (const float*)d_in[2];
    const float* WV   = (const float*)d_in[3];
    const float* WOw  = (const float*)d_in[4];
    const float* WOb  = (const float*)d_in[5];
    const float* FF1w = (const float*)d_in[6];
    const float* FF1b = (const float*)d_in[7];
    const float* FF2w = (const float*)d_in[8];
    const float* FF2b = (const float*)d_in[9];

    float* SA  = (float*)d_out;
    float* OUT = (float*)d_out + SA_ELEMS;

    float *WqkvT, *QKV, *Z, *ATT, *H1;
    cudaGetSymbolAddress((void**)&WqkvT, g_WqkvT);
    cudaGetSymbolAddress((void**)&QKV, g_QKV);
    cudaGetSymbolAddress((void**)&Z, g_Z);
    cudaGetSymbolAddress((void**)&ATT, g_ATT);
    cudaGetSymbolAddress((void**)&H1, g_H1);

    // 1. pack QKV weights transposed into [3072, 1024]
    pack_w_kernel<<<(3 * D * D + 255) / 256, 256>>>(WQ, WK, WV);

    // 2. QKV projection (tensor cores, tf32)
    tf32gemm_kernel<0><<<dim3(3 * D / 128, S / 128), 256>>>(
        X, WqkvT, nullptr, nullptr, QKV, S, 3 * D, D);

    // 3. scores (+ALiBi, causal) into SA region (tensor cores, 3xTF32)
    scores_tc_kernel<<<dim3(S / 128, S / 128, H), 256>>>(QKV, SA);

    // 4. in-place softmax over causal prefix of each row
    softmax_kernel<<<H * S, 256>>>(SA);

    // 5. z = SA @ V (tensor cores, tf32)
    av_tc_kernel<<<dim3(S / 128, H), 256>>>(SA, QKV, Z);

    // 6. attouts = X + Z @ WO_w^T + WO_b
    tf32gemm_kernel<1><<<dim3(D / 128, S / 128), 256>>>(
        Z, WOw, WOb, X, ATT, S, D, D);

    // 7. H1 = relu(ATT @ FF1_w^T + FF1_b)
    tf32gemm_kernel<2><<<dim3(DFF / 128, S / 128), 256>>>(
        ATT, FF1w, FF1b, nullptr, H1, S, DFF, D);

    // 8. out = ATT + H1 @ FF2_w^T + FF2_b
    tf32gemm_kernel<1><<<dim3(D / 128, S / 128), 256>>>(
        H1, FF2w, FF2b, ATT, OUT, S, D, DFF);
}

// round 4
// speedup vs baseline: 2.1823x; 1.1364x over previous
#include <cuda_runtime.h>
#include <cstdint>

// Problem constants
#define S 2048
#define D 1024
#define H 16
#define DI 64
#define DV 64
#define DFF 4096
#define SA_ELEMS ((size_t)H * S * S)   // 67108864

// -------------------- scratch (device globals) -----------------------------
__device__ float g_WqkvT[(size_t)(3 * D) * D];   // packed transposed [3072, 1024]
__device__ float g_QKV[(size_t)S * 3 * D];       // [S, 3072]  (Q | K | V)
__device__ float g_Z[(size_t)S * D];             // [S, H*DV]
__device__ float g_ATT[(size_t)S * D];
__device__ float g_H1[(size_t)S * DFF];

// -------------------- helpers ---------------------------------------------
__device__ __forceinline__ unsigned f2tf32(float x) {
    unsigned u;
    asm("cvt.rna.tf32.f32 %0, %1;" : "=r"(u) : "f"(x));
    return u;
}

__device__ __forceinline__ void ldsm_x4(unsigned& r0, unsigned& r1, unsigned& r2, unsigned& r3,
                                        const float* p) {
    unsigned addr = (unsigned)__cvta_generic_to_shared(p);
    asm volatile("ldmatrix.sync.aligned.m8n8.x4.shared.b16 {%0,%1,%2,%3}, [%4];"
                 : "=r"(r0), "=r"(r1), "=r"(r2), "=r"(r3) : "r"(addr));
}

__device__ __forceinline__ void mma_tf32(float* c, const unsigned* a, const unsigned* b) {
    asm volatile(
        "mma.sync.aligned.m16n8k8.row.col.f32.tf32.tf32.f32 "
        "{%0,%1,%2,%3}, {%4,%5,%6,%7}, {%8,%9}, {%0,%1,%2,%3};"
        : "+f"(c[0]), "+f"(c[1]), "+f"(c[2]), "+f"(c[3])
        : "r"(a[0]), "r"(a[1]), "r"(a[2]), "r"(a[3]), "r"(b[0]), "r"(b[1]));
}

__device__ __forceinline__ float4 cvt4(float4 v) {
    float4 t;
    t.x = __uint_as_float(f2tf32(v.x)); t.y = __uint_as_float(f2tf32(v.y));
    t.z = __uint_as_float(f2tf32(v.z)); t.w = __uint_as_float(f2tf32(v.w));
    return t;
}

// -------------------- pack WQ/WK/WV transposed: [3072, 1024] ---------------
__global__ void pack_w_kernel(const float* __restrict__ WQ,
                              const float* __restrict__ WK,
                              const float* __restrict__ WV) {
    int idx = blockIdx.x * 256 + threadIdx.x;   // n*1024 + d
    if (idx >= 3 * D * D) return;
    int d = idx & 1023;
    int n = idx >> 10;
    int sect = n >> 10;
    int nn = n & 1023;
    int h = nn >> 6, e = nn & 63;
    const float* W = (sect == 0) ? WQ : (sect == 1) ? WK : WV;
    g_WqkvT[idx] = W[((size_t)h * D + d) * 64 + e];
}

// ---------- tf32 tensor-core GEMM, double-buffered: C = A[MxK]*B[NxK]^T ----
// EPI: 0 none ; 1 = +bias[n] + res[m,n] ; 2 = relu(acc + bias[n])
template <int EPI>
__global__ __launch_bounds__(256)
void tf32gemm_kernel(const float* __restrict__ A, const float* __restrict__ B,
                     const float* __restrict__ bias, const float* __restrict__ res,
                     float* __restrict__ C, int M, int N, int K) {
    const int BM = 128, BK = 16, LDS_ = 20;
    __shared__ float As[2][BM * LDS_];
    __shared__ float Bs[2][BM * LDS_];

    int tid = threadIdx.x;
    int lane = tid & 31, warp = tid >> 5;
    int warpM = warp >> 1, warpN = warp & 1;     // 4 x 2 warp grid
    int bm = blockIdx.y * BM, bn = blockIdx.x * BM;

    float acc[2][8][4];
#pragma unroll
    for (int i = 0; i < 2; i++)
#pragma unroll
        for (int j = 0; j < 8; j++)
#pragma unroll
            for (int r = 0; r < 4; r++) acc[i][j][r] = 0.f;

    int a_row = warpM * 32 + (lane & 15);
    int a_col = (lane >> 4) * 4;
    int b_row = warpN * 64 + (lane & 7) + ((lane >> 4) << 3);
    int b_col = ((lane >> 3) & 1) * 4;

    // per-thread load coords: 2 rows (r0 = tid>>2, r1 = r0+64), 4 cols each
    int ld_r0 = tid >> 2, ld_c4 = (tid & 3) * 4;
    const float* Ap = A + (size_t)(bm + ld_r0) * K + ld_c4;
    const float* Bp = B + (size_t)(bn + ld_r0) * K + ld_c4;
    size_t rowoff = (size_t)64 * K;

    // prologue: load tile 0 and store to buffer 0
    {
        float4 a0 = *(const float4*)(Ap);
        float4 a1 = *(const float4*)(Ap + rowoff);
        float4 b0 = *(const float4*)(Bp);
        float4 b1 = *(const float4*)(Bp + rowoff);
        *(float4*)&As[0][ld_r0 * LDS_ + ld_c4] = cvt4(a0);
        *(float4*)&As[0][(ld_r0 + 64) * LDS_ + ld_c4] = cvt4(a1);
        *(float4*)&Bs[0][ld_r0 * LDS_ + ld_c4] = cvt4(b0);
        *(float4*)&Bs[0][(ld_r0 + 64) * LDS_ + ld_c4] = cvt4(b1);
    }
    __syncthreads();

    int buf = 0;
    for (int k0 = 0; k0 < K; k0 += BK) {
        bool has_next = (k0 + BK) < K;
        float4 pa0, pa1, pb0, pb1;
        if (has_next) {   // issue next tile's global loads early
            const float* Ap2 = Ap + k0 + BK;
            const float* Bp2 = Bp + k0 + BK;
            pa0 = *(const float4*)(Ap2);
            pa1 = *(const float4*)(Ap2 + rowoff);
            pb0 = *(const float4*)(Bp2);
            pb1 = *(const float4*)(Bp2 + rowoff);
        }

        const float* Asb = As[buf];
        const float* Bsb = Bs[buf];
#pragma unroll
        for (int ks = 0; ks < 2; ks++) {
            unsigned af[2][4];
            unsigned bf[8][2];
#pragma unroll
            for (int mt = 0; mt < 2; mt++) {
                ldsm_x4(af[mt][0], af[mt][1], af[mt][2], af[mt][3],
                        &Asb[(a_row + mt * 16) * LDS_ + ks * 8 + a_col]);
            }
#pragma unroll
            for (int np = 0; np < 4; np++) {
                ldsm_x4(bf[2 * np][0], bf[2 * np][1], bf[2 * np + 1][0], bf[2 * np + 1][1],
                        &Bsb[(b_row + np * 16) * LDS_ + ks * 8 + b_col]);
            }
#pragma unroll
            for (int mt = 0; mt < 2; mt++)
#pragma unroll
                for (int nt = 0; nt < 8; nt++)
                    mma_tf32(acc[mt][nt], af[mt], bf[nt]);
        }

        if (has_next) {
            float* Asn = As[buf ^ 1];
            float* Bsn = Bs[buf ^ 1];
            *(float4*)&Asn[ld_r0 * LDS_ + ld_c4] = cvt4(pa0);
            *(float4*)&Asn[(ld_r0 + 64) * LDS_ + ld_c4] = cvt4(pa1);
            *(float4*)&Bsn[ld_r0 * LDS_ + ld_c4] = cvt4(pb0);
            *(float4*)&Bsn[(ld_r0 + 64) * LDS_ + ld_c4] = cvt4(pb1);
        }
        __syncthreads();
        buf ^= 1;
    }

    int g = lane >> 2, c2 = (lane & 3) * 2;
#pragma unroll
    for (int mt = 0; mt < 2; mt++) {
#pragma unroll
        for (int half = 0; half < 2; half++) {
            int m = bm + warpM * 32 + mt * 16 + g + half * 8;
#pragma unroll
            for (int nt = 0; nt < 8; nt++) {
                int n = bn + warpN * 64 + nt * 8 + c2;
                float v0 = acc[mt][nt][half * 2 + 0];
                float v1 = acc[mt][nt][half * 2 + 1];
                if (EPI >= 1) { v0 += bias[n]; v1 += bias[n + 1]; }
                if (EPI == 1) {
                    float2 rr = *(const float2*)(res + (size_t)m * N + n);
                    v0 += rr.x; v1 += rr.y;
                }
                if (EPI == 2) { v0 = fmaxf(v0, 0.f); v1 = fmaxf(v1, 0.f); }
                float2 o; o.x = v0; o.y = v1;
                *(float2*)(C + (size_t)m * N + n) = o;
            }
        }
    }
}

// -------------------- scores (tensor cores, 3xTF32 for fp32 accuracy) ------
__global__ __launch_bounds__(256)
void scores_tc_kernel(const float* __restrict__ QKV, float* __restrict__ SA) {
    const int LDS_ = 20;
    int jt = blockIdx.x, it = blockIdx.y, h = blockIdx.z;
    int bm = it * 128, bn = jt * 128;
    float* out = SA + ((size_t)h * S + bm) * S + bn;
    int tid = threadIdx.x;

    if (jt > it) {   // strictly above diagonal at 128-granularity: zeros
#pragma unroll
        for (int r = 0; r < 16; r++) {
            int id = tid + r * 256;
            int row = id >> 5, c4 = (id & 31) * 4;
            *(float4*)(out + (size_t)row * S + c4) = make_float4(0.f, 0.f, 0.f, 0.f);
        }
        return;
    }

    __shared__ float Qh[128 * LDS_], Ql[128 * LDS_];
    __shared__ float Kh[128 * LDS_], Kl[128 * LDS_];

    int lane = tid & 31, warp = tid >> 5;
    int warpM = warp >> 1, warpN = warp & 1;

    float acc[2][8][4];
#pragma unroll
    for (int i = 0; i < 2; i++)
#pragma unroll
        for (int j = 0; j < 8; j++)
#pragma unroll
            for (int r = 0; r < 4; r++) acc[i][j][r] = 0.f;

    int a_row = warpM * 32 + (lane & 15);
    int a_col = (lane >> 4) * 4;
    int b_row = warpN * 64 + (lane & 7) + ((lane >> 4) << 3);
    int b_col = ((lane >> 3) & 1) * 4;

    const float* Qb = QKV + (size_t)bm * (3 * D) + h * 64;
    const float* Kb = QKV + (size_t)bn * (3 * D) + D + h * 64;

    for (int kc = 0; kc < 4; kc++) {
#pragma unroll
        for (int i = 0; i < 2; i++) {
            int id = tid + i * 256;
            int row = id >> 2, c4 = (id & 3) * 4;
            float4 q = *(const float4*)(Qb + (size_t)row * (3 * D) + kc * 16 + c4);
            float4 k = *(const float4*)(Kb + (size_t)row * (3 * D) + kc * 16 + c4);
            float4 qh = cvt4(q), kh = cvt4(k);
            float4 ql, kl;
            ql.x = __uint_as_float(f2tf32(q.x - qh.x)); ql.y = __uint_as_float(f2tf32(q.y - qh.y));
            ql.z = __uint_as_float(f2tf32(q.z - qh.z)); ql.w = __uint_as_float(f2tf32(q.w - qh.w));
            kl.x = __uint_as_float(f2tf32(k.x - kh.x)); kl.y = __uint_as_float(f2tf32(k.y - kh.y));
            kl.z = __uint_as_float(f2tf32(k.z - kh.z)); kl.w = __uint_as_float(f2tf32(k.w - kh.w));
            *(float4*)&Qh[row * LDS_ + c4] = qh;
            *(float4*)&Ql[row * LDS_ + c4] = ql;
            *(float4*)&Kh[row * LDS_ + c4] = kh;
            *(float4*)&Kl[row * LDS_ + c4] = kl;
        }
        __syncthreads();

#pragma unroll
        for (int ks = 0; ks < 2; ks++) {
            unsigned afh[2][4], afl[2][4];
            unsigned bfh[8][2], bfl[8][2];
#pragma unroll
            for (int mt = 0; mt < 2; mt++) {
                ldsm_x4(afh[mt][0], afh[mt][1], afh[mt][2], afh[mt][3],
                        &Qh[(a_row + mt * 16) * LDS_ + ks * 8 + a_col]);
                ldsm_x4(afl[mt][0], afl[mt][1], afl[mt][2], afl[mt][3],
                        &Ql[(a_row + mt * 16) * LDS_ + ks * 8 + a_col]);
            }
#pragma unroll
            for (int np = 0; np < 4; np++) {
                ldsm_x4(bfh[2 * np][0], bfh[2 * np][1], bfh[2 * np + 1][0], bfh[2 * np + 1][1],
                        &Kh[(b_row + np * 16) * LDS_ + ks * 8 + b_col]);
                ldsm_x4(bfl[2 * np][0], bfl[2 * np][1], bfl[2 * np + 1][0], bfl[2 * np + 1][1],
                        &Kl[(b_row + np * 16) * LDS_ + ks * 8 + b_col]);
            }
#pragma unroll
            for (int mt = 0; mt < 2; mt++)
#pragma unroll
                for (int nt = 0; nt < 8; nt++) {
                    mma_tf32(acc[mt][nt], afh[mt], bfh[nt]);
                    mma_tf32(acc[mt][nt], afh[mt], bfl[nt]);
                    mma_tf32(acc[mt][nt], afl[mt], bfh[nt]);
                }
        }
        __syncthreads();
    }

    float slope = exp2f(-0.5f * (float)(h + 1));
    int g = lane >> 2, c2 = (lane & 3) * 2;
#pragma unroll
    for (int mt = 0; mt < 2; mt++) {
#pragma unroll
        for (int half = 0; half < 2; half++) {
            int li = warpM * 32 + mt * 16 + g + half * 8;
            int gi = bm + li;
#pragma unroll
            for (int nt = 0; nt < 8; nt++) {
                int lj = warpN * 64 + nt * 8 + c2;
                int gj = bn + lj;
                float v0 = acc[mt][nt][half * 2 + 0];
                float v1 = acc[mt][nt][half * 2 + 1];
                v0 = (gj <= gi) ? (v0 * 0.125f - (float)(gi - gj) * slope) : 0.f;
                v1 = (gj + 1 <= gi) ? (v1 * 0.125f - (float)(gi - gj - 1) * slope) : 0.f;
                float2 o; o.x = v0; o.y = v1;
                *(float2*)(out + (size_t)li * S + lj) = o;
            }
        }
    }
}

// -------------------- in-place causal row softmax --------------------------
__global__ __launch_bounds__(256)
void softmax_kernel(float* __restrict__ SA) {
    int row = blockIdx.x;           // h*S + i
    int i = row & (S - 1);
    float* p = SA + (size_t)row * S;
    int t = threadIdx.x;
    __shared__ float red[8];

    float v[8];
    float mx = -1e30f;
#pragma unroll
    for (int r = 0; r < 8; r++) {
        int j = t + r * 256;
        float x = (j <= i) ? p[j] : -1e30f;
        v[r] = x;
        mx = fmaxf(mx, x);
    }
#pragma unroll
    for (int o = 16; o > 0; o >>= 1) mx = fmaxf(mx, __shfl_xor_sync(0xffffffffu, mx, o));
    if ((t & 31) == 0) red[t >> 5] = mx;
    __syncthreads();
    float bm = red[0];
#pragma unroll
    for (int w = 1; w < 8; w++) bm = fmaxf(bm, red[w]);
    __syncthreads();

    float sum = 0.f;
#pragma unroll
    for (int r = 0; r < 8; r++) {
        float e = __expf(v[r] - bm);
        v[r] = e;
        sum += e;
    }
#pragma unroll
    for (int o = 16; o > 0; o >>= 1) sum += __shfl_xor_sync(0xffffffffu, sum, o);
    if ((t & 31) == 0) red[t >> 5] = sum;
    __syncthreads();
    float bs = 0.f;
#pragma unroll
    for (int w = 0; w < 8; w++) bs += red[w];
    float inv = 1.f / bs;
#pragma unroll
    for (int r = 0; r < 8; r++) {
        int j = t + r * 256;
        if (j <= i) p[j] = v[r] * inv;
    }
}

// -------------------- z = SA @ V (tensor cores, tf32) ----------------------
__global__ __launch_bounds__(256)
void av_tc_kernel(const float* __restrict__ SA, const float* __restrict__ QKV,
                  float* __restrict__ Z) {
    const int LDS_ = 20;
    int bi = blockIdx.x, h = blockIdx.y;
    int bm = bi * 128;
    int tid = threadIdx.x;
    int lane = tid & 31, warp = tid >> 5;

    __shared__ float SAs[128 * LDS_];
    __shared__ float Vs[64 * LDS_];

    float acc[8][4];
#pragma unroll
    for (int j = 0; j < 8; j++)
#pragma unroll
        for (int r = 0; r < 4; r++) acc[j][r] = 0.f;

    int a_row = warp * 16 + (lane & 15);
    int a_col = (lane >> 4) * 4;
    int b_row = (lane & 7) + ((lane >> 4) << 3);
    int b_col = ((lane >> 3) & 1) * 4;

    const float* SAb = SA + ((size_t)h * S + bm) * S;
    const float* Vb = QKV + 2 * D + (size_t)h * 64;

    int nchunks = (bm + 128) / 16;
    for (int kc = 0; kc < nchunks; kc++) {
        int k0 = kc * 16;
#pragma unroll
        for (int i = 0; i < 2; i++) {
            int id = tid + i * 256;
            int row = id >> 2, c4 = (id & 3) * 4;
            float4 a = *(const float4*)(SAb + (size_t)row * S + k0 + c4);
            *(float4*)&SAs[row * LDS_ + c4] = cvt4(a);
        }
        {
            int jloc = tid >> 6, v = tid & 63;
#pragma unroll
            for (int i = 0; i < 4; i++) {
                int jj = jloc + i * 4;
                float x = Vb[(size_t)(k0 + jj) * (3 * D) + v];
                Vs[v * LDS_ + jj] = __uint_as_float(f2tf32(x));
            }
        }
        __syncthreads();

#pragma unroll
        for (int ks = 0; ks < 2; ks++) {
            unsigned af[4];
            unsigned bf[8][2];
            ldsm_x4(af[0], af[1], af[2], af[3],
                    &SAs[a_row * LDS_ + ks * 8 + a_col]);
#pragma unroll
            for (int np = 0; np < 4; np++) {
                ldsm_x4(bf[2 * np][0], bf[2 * np][1], bf[2 * np + 1][0], bf[2 * np + 1][1],
                        &Vs[(b_row + np * 16) * LDS_ + ks * 8 + b_col]);
            }
#pragma unroll
            for (int nt = 0; nt < 8; nt++)
                mma_tf32(acc[nt], af, bf[nt]);
        }
        __syncthreads();
    }

    int g = lane >> 2, c2 = (lane & 3) * 2;
#pragma unroll
    for (int half = 0; half < 2; half++) {
        int m = bm + warp * 16 + g + half * 8;
#pragma unroll
        for (int nt = 0; nt < 8; nt++) {
            int n = h * 64 + nt * 8 + c2;
            float2 o;
            o.x = acc[nt][half * 2 + 0];
            o.y = acc[nt][half * 2 + 1];
            *(float2*)(Z + (size_t)m * D + n) = o;
        }
    }
}

// --------------------------- launch ---------------------------------------
extern "C" void kernel_launch(void* const* d_in, const int* in_sizes, int n_in,
                              void* d_out, int out_size) {
    const float* X    = (const float*)d_in[0];
    const float* WQ   = (const float*)d_in[1];
    const float* WK   = (const float*)d_in[2];
    const float* WV   = (const float*)d_in[3];
    const float* WOw  = (const float*)d_in[4];
    const float* WOb  = (const float*)d_in[5];
    const float* FF1w = (const float*)d_in[6];
    const float* FF1b = (const float*)d_in[7];
    const float* FF2w = (const float*)d_in[8];
    const float* FF2b = (const float*)d_in[9];

    float* SA  = (float*)d_out;
    float* OUT = (float*)d_out + SA_ELEMS;

    float *WqkvT, *QKV, *Z, *ATT, *H1;
    cudaGetSymbolAddress((void**)&WqkvT, g_WqkvT);
    cudaGetSymbolAddress((void**)&QKV, g_QKV);
    cudaGetSymbolAddress((void**)&Z, g_Z);
    cudaGetSymbolAddress((void**)&ATT, g_ATT);
    cudaGetSymbolAddress((void**)&H1, g_H1);

    // 1. pack QKV weights transposed into [3072, 1024]
    pack_w_kernel<<<(3 * D * D + 255) / 256, 256>>>(WQ, WK, WV);

    // 2. QKV projection (tensor cores, tf32, pipelined)
    tf32gemm_kernel<0><<<dim3(3 * D / 128, S / 128), 256>>>(
        X, WqkvT, nullptr, nullptr, QKV, S, 3 * D, D);

    // 3. scores (+ALiBi, causal) into SA region (tensor cores, 3xTF32)
    scores_tc_kernel<<<dim3(S / 128, S / 128, H), 256>>>(QKV, SA);

    // 4. in-place softmax over causal prefix of each row
    softmax_kernel<<<H * S, 256>>>(SA);

    // 5. z = SA @ V (tensor cores, tf32)
    av_tc_kernel<<<dim3(S / 128, H), 256>>>(SA, QKV, Z);

    // 6. attouts = X + Z @ WO_w^T + WO_b
    tf32gemm_kernel<1><<<dim3(D / 128, S / 128), 256>>>(
        Z, WOw, WOb, X, ATT, S, D, D);

    // 7. H1 = relu(ATT @ FF1_w^T + FF1_b)
    tf32gemm_kernel<2><<<dim3(DFF / 128, S / 128), 256>>>(
        ATT, FF1w, FF1b, nullptr, H1, S, DFF, D);

    // 8. out = ATT + H1 @ FF2_w^T + FF2_b
    tf32gemm_kernel<1><<<dim3(D / 128, S / 128), 256>>>(
        H1, FF2w, FF2b, ATT, OUT, S, DFF == 0 ? D : D, DFF);
}

// round 5
// speedup vs baseline: 2.2970x; 1.0526x over previous
#include <cuda_runtime.h>
#include <cstdint>

// Problem constants
#define S 2048
#define D 1024
#define H 16
#define DI 64
#define DV 64
#define DFF 4096
#define SA_ELEMS ((size_t)H * S * S)   // 67108864

// -------------------- scratch (device globals) -----------------------------
__device__ float g_WqkvT[(size_t)(3 * D) * D];   // packed transposed, tf32-rounded
__device__ float g_QKV[(size_t)S * 3 * D];       // [S, 3072] full fp32
__device__ float g_Z[(size_t)S * D];             // tf32-rounded (av epilogue)
__device__ float g_ATT[(size_t)S * D];           // full fp32 (residual)
__device__ float g_ATTc[(size_t)S * D];          // tf32-rounded copy
__device__ float g_H1[(size_t)S * DFF];          // tf32-rounded (FF1 epilogue)
__device__ float g_Xc[(size_t)S * D];            // tf32-rounded input
__device__ float g_WOc[(size_t)D * D];           // tf32-rounded WO_w
__device__ float g_FF1c[(size_t)DFF * D];        // tf32-rounded FF1_w
__device__ float g_FF2c[(size_t)D * DFF];        // tf32-rounded FF2_w

// -------------------- helpers ---------------------------------------------
__device__ __forceinline__ unsigned f2tf32(float x) {
    unsigned u;
    asm("cvt.rna.tf32.f32 %0, %1;" : "=r"(u) : "f"(x));
    return u;
}
__device__ __forceinline__ float f2tf32f(float x) { return __uint_as_float(f2tf32(x)); }

__device__ __forceinline__ float4 cvt4(float4 v) {
    float4 t;
    t.x = f2tf32f(v.x); t.y = f2tf32f(v.y);
    t.z = f2tf32f(v.z); t.w = f2tf32f(v.w);
    return t;
}

__device__ __forceinline__ void ldsm_x4(unsigned& r0, unsigned& r1, unsigned& r2, unsigned& r3,
                                        const float* p) {
    unsigned addr = (unsigned)__cvta_generic_to_shared(p);
    asm volatile("ldmatrix.sync.aligned.m8n8.x4.shared.b16 {%0,%1,%2,%3}, [%4];"
                 : "=r"(r0), "=r"(r1), "=r"(r2), "=r"(r3) : "r"(addr));
}

__device__ __forceinline__ void mma_tf32(float* c, const unsigned* a, const unsigned* b) {
    asm volatile(
        "mma.sync.aligned.m16n8k8.row.col.f32.tf32.tf32.f32 "
        "{%0,%1,%2,%3}, {%4,%5,%6,%7}, {%8,%9}, {%0,%1,%2,%3};"
        : "+f"(c[0]), "+f"(c[1]), "+f"(c[2]), "+f"(c[3])
        : "r"(a[0]), "r"(a[1]), "r"(a[2]), "r"(a[3]), "r"(b[0]), "r"(b[1]));
}

__device__ __forceinline__ void cp_async16(float* smem_dst, const float* gsrc) {
    unsigned dst = (unsigned)__cvta_generic_to_shared(smem_dst);
    asm volatile("cp.async.cg.shared.global [%0], [%1], 16;" :: "r"(dst), "l"(gsrc));
}
__device__ __forceinline__ void cp_commit() {
    asm volatile("cp.async.commit_group;");
}
template <int N>
__device__ __forceinline__ void cp_wait() {
    asm volatile("cp.async.wait_group %0;" :: "n"(N));
}

// -------------------- elementwise tf32 round (pre-convert) -----------------
__global__ void cvt_kernel(const float* __restrict__ in, float* __restrict__ out, int n4) {
    int i = blockIdx.x * 256 + threadIdx.x;
    if (i >= n4) return;
    float4 v = *(const float4*)(in + (size_t)i * 4);
    *(float4*)(out + (size_t)i * 4) = cvt4(v);
}

// -------------------- pack WQ/WK/WV transposed + round: [3072, 1024] -------
__global__ void pack_w_kernel(const float* __restrict__ WQ,
                              const float* __restrict__ WK,
                              const float* __restrict__ WV) {
    int idx = blockIdx.x * 256 + threadIdx.x;   // n*1024 + d
    if (idx >= 3 * D * D) return;
    int d = idx & 1023;
    int n = idx >> 10;
    int sect = n >> 10;
    int nn = n & 1023;
    int h = nn >> 6, e = nn & 63;
    const float* W = (sect == 0) ? WQ : (sect == 1) ? WK : WV;
    g_WqkvT[idx] = f2tf32f(W[((size_t)h * D + d) * 64 + e]);
}

// ---- tf32 GEMM, cp.async 2-stage: C = A[MxK]*B[NxK]^T (operands pre-rounded)
// EPI: 0 = write C
//      1 = C = acc + bias[n] + res[m,n]
//      2 = C = tf32(relu(acc + bias[n]))
//      3 = C = acc + bias[n] + res[m,n], C2 = tf32(C)
template <int EPI>
__global__ __launch_bounds__(256)
void tf32gemm_ca(const float* __restrict__ A, const float* __restrict__ B,
                 const float* __restrict__ bias, const float* __restrict__ res,
                 float* __restrict__ C, float* __restrict__ C2,
                 int M, int N, int K) {
    const int BM = 128, BK = 16, LDS_ = 20;
    __shared__ float As[2][BM * LDS_];
    __shared__ float Bs[2][BM * LDS_];

    int tid = threadIdx.x;
    int lane = tid & 31, warp = tid >> 5;
    int warpM = warp >> 1, warpN = warp & 1;     // 4 x 2 warp grid
    int bm = blockIdx.y * BM, bn = blockIdx.x * BM;

    float acc[2][8][4];
#pragma unroll
    for (int i = 0; i < 2; i++)
#pragma unroll
        for (int j = 0; j < 8; j++)
#pragma unroll
            for (int r = 0; r < 4; r++) acc[i][j][r] = 0.f;

    int a_row = warpM * 32 + (lane & 15);
    int a_col = (lane >> 4) * 4;
    int b_row = warpN * 64 + (lane & 7) + ((lane >> 4) << 3);
    int b_col = ((lane >> 3) & 1) * 4;

    // per-thread load coords: rows (tid>>2, +64), 4 floats each
    int ld_r0 = tid >> 2, ld_c4 = (tid & 3) * 4;
    const float* Ap = A + (size_t)(bm + ld_r0) * K + ld_c4;
    const float* Bp = B + (size_t)(bn + ld_r0) * K + ld_c4;
    size_t rowoff = (size_t)64 * K;

    int s0a = ld_r0 * LDS_ + ld_c4;
    int s1a = (ld_r0 + 64) * LDS_ + ld_c4;

    // prologue: stage 0
    cp_async16(&As[0][s0a], Ap);
    cp_async16(&As[0][s1a], Ap + rowoff);
    cp_async16(&Bs[0][s0a], Bp);
    cp_async16(&Bs[0][s1a], Bp + rowoff);
    cp_commit();

    int nk = K / BK;
    for (int kt = 0; kt < nk; kt++) {
        if (kt + 1 < nk) {
            int buf = (kt + 1) & 1;
            const float* Ap2 = Ap + (size_t)(kt + 1) * BK;
            const float* Bp2 = Bp + (size_t)(kt + 1) * BK;
            cp_async16(&As[buf][s0a], Ap2);
            cp_async16(&As[buf][s1a], Ap2 + rowoff);
            cp_async16(&Bs[buf][s0a], Bp2);
            cp_async16(&Bs[buf][s1a], Bp2 + rowoff);
            cp_commit();
            cp_wait<1>();
        } else {
            cp_wait<0>();
        }
        __syncthreads();

        const float* Asb = As[kt & 1];
        const float* Bsb = Bs[kt & 1];
#pragma unroll
        for (int ks = 0; ks < 2; ks++) {
            unsigned af[2][4];
            unsigned bf[8][2];
#pragma unroll
            for (int mt = 0; mt < 2; mt++) {
                ldsm_x4(af[mt][0], af[mt][1], af[mt][2], af[mt][3],
                        &Asb[(a_row + mt * 16) * LDS_ + ks * 8 + a_col]);
            }
#pragma unroll
            for (int np = 0; np < 4; np++) {
                ldsm_x4(bf[2 * np][0], bf[2 * np][1], bf[2 * np + 1][0], bf[2 * np + 1][1],
                        &Bsb[(b_row + np * 16) * LDS_ + ks * 8 + b_col]);
            }
#pragma unroll
            for (int mt = 0; mt < 2; mt++)
#pragma unroll
                for (int nt = 0; nt < 8; nt++)
                    mma_tf32(acc[mt][nt], af[mt], bf[nt]);
        }
        __syncthreads();
    }

    int g = lane >> 2, c2 = (lane & 3) * 2;
#pragma unroll
    for (int mt = 0; mt < 2; mt++) {
#pragma unroll
        for (int half = 0; half < 2; half++) {
            int m = bm + warpM * 32 + mt * 16 + g + half * 8;
#pragma unroll
            for (int nt = 0; nt < 8; nt++) {
                int n = bn + warpN * 64 + nt * 8 + c2;
                float v0 = acc[mt][nt][half * 2 + 0];
                float v1 = acc[mt][nt][half * 2 + 1];
                if (EPI >= 1) { v0 += bias[n]; v1 += bias[n + 1]; }
                if (EPI == 1 || EPI == 3) {
                    float2 rr = *(const float2*)(res + (size_t)m * N + n);
                    v0 += rr.x; v1 += rr.y;
                }
                if (EPI == 2) {
                    v0 = f2tf32f(fmaxf(v0, 0.f));
                    v1 = f2tf32f(fmaxf(v1, 0.f));
                }
                float2 o; o.x = v0; o.y = v1;
                *(float2*)(C + (size_t)m * N + n) = o;
                if (EPI == 3) {
                    float2 oc; oc.x = f2tf32f(v0); oc.y = f2tf32f(v1);
                    *(float2*)(C2 + (size_t)m * N + n) = oc;
                }
            }
        }
    }
}

// -------------------- scores (tensor cores, 3xTF32 for fp32 accuracy) ------
__global__ __launch_bounds__(256)
void scores_tc_kernel(const float* __restrict__ QKV, float* __restrict__ SA) {
    const int LDS_ = 20;
    int jt = blockIdx.x, it = blockIdx.y, h = blockIdx.z;
    int bm = it * 128, bn = jt * 128;
    float* out = SA + ((size_t)h * S + bm) * S + bn;
    int tid = threadIdx.x;

    if (jt > it) {   // strictly above diagonal at 128-granularity: zeros
#pragma unroll
        for (int r = 0; r < 16; r++) {
            int id = tid + r * 256;
            int row = id >> 5, c4 = (id & 31) * 4;
            *(float4*)(out + (size_t)row * S + c4) = make_float4(0.f, 0.f, 0.f, 0.f);
        }
        return;
    }

    __shared__ float Qh[128 * LDS_], Ql[128 * LDS_];
    __shared__ float Kh[128 * LDS_], Kl[128 * LDS_];

    int lane = tid & 31, warp = tid >> 5;
    int warpM = warp >> 1, warpN = warp & 1;

    float acc[2][8][4];
#pragma unroll
    for (int i = 0; i < 2; i++)
#pragma unroll
        for (int j = 0; j < 8; j++)
#pragma unroll
            for (int r = 0; r < 4; r++) acc[i][j][r] = 0.f;

    int a_row = warpM * 32 + (lane & 15);
    int a_col = (lane >> 4) * 4;
    int b_row = warpN * 64 + (lane & 7) + ((lane >> 4) << 3);
    int b_col = ((lane >> 3) & 1) * 4;

    const float* Qb = QKV + (size_t)bm * (3 * D) + h * 64;
    const float* Kb = QKV + (size_t)bn * (3 * D) + D + h * 64;

    for (int kc = 0; kc < 4; kc++) {
#pragma unroll
        for (int i = 0; i < 2; i++) {
            int id = tid + i * 256;
            int row = id >> 2, c4 = (id & 3) * 4;
            float4 q = *(const float4*)(Qb + (size_t)row * (3 * D) + kc * 16 + c4);
            float4 k = *(const float4*)(Kb + (size_t)row * (3 * D) + kc * 16 + c4);
            float4 qh = cvt4(q), kh = cvt4(k);
            float4 ql, kl;
            ql.x = f2tf32f(q.x - qh.x); ql.y = f2tf32f(q.y - qh.y);
            ql.z = f2tf32f(q.z - qh.z); ql.w = f2tf32f(q.w - qh.w);
            kl.x = f2tf32f(k.x - kh.x); kl.y = f2tf32f(k.y - kh.y);
            kl.z = f2tf32f(k.z - kh.z); kl.w = f2tf32f(k.w - kh.w);
            *(float4*)&Qh[row * LDS_ + c4] = qh;
            *(float4*)&Ql[row * LDS_ + c4] = ql;
            *(float4*)&Kh[row * LDS_ + c4] = kh;
            *(float4*)&Kl[row * LDS_ + c4] = kl;
        }
        __syncthreads();

#pragma unroll
        for (int ks = 0; ks < 2; ks++) {
            unsigned afh[2][4], afl[2][4];
            unsigned bfh[8][2], bfl[8][2];
#pragma unroll
            for (int mt = 0; mt < 2; mt++) {
                ldsm_x4(afh[mt][0], afh[mt][1], afh[mt][2], afh[mt][3],
                        &Qh[(a_row + mt * 16) * LDS_ + ks * 8 + a_col]);
                ldsm_x4(afl[mt][0], afl[mt][1], afl[mt][2], afl[mt][3],
                        &Ql[(a_row + mt * 16) * LDS_ + ks * 8 + a_col]);
            }
#pragma unroll
            for (int np = 0; np < 4; np++) {
                ldsm_x4(bfh[2 * np][0], bfh[2 * np][1], bfh[2 * np + 1][0], bfh[2 * np + 1][1],
                        &Kh[(b_row + np * 16) * LDS_ + ks * 8 + b_col]);
                ldsm_x4(bfl[2 * np][0], bfl[2 * np][1], bfl[2 * np + 1][0], bfl[2 * np + 1][1],
                        &Kl[(b_row + np * 16) * LDS_ + ks * 8 + b_col]);
            }
#pragma unroll
            for (int mt = 0; mt < 2; mt++)
#pragma unroll
                for (int nt = 0; nt < 8; nt++) {
                    mma_tf32(acc[mt][nt], afh[mt], bfh[nt]);
                    mma_tf32(acc[mt][nt], afh[mt], bfl[nt]);
                    mma_tf32(acc[mt][nt], afl[mt], bfh[nt]);
                }
        }
        __syncthreads();
    }

    float slope = exp2f(-0.5f * (float)(h + 1));
    int g = lane >> 2, c2 = (lane & 3) * 2;
#pragma unroll
    for (int mt = 0; mt < 2; mt++) {
#pragma unroll
        for (int half = 0; half < 2; half++) {
            int li = warpM * 32 + mt * 16 + g + half * 8;
            int gi = bm + li;
#pragma unroll
            for (int nt = 0; nt < 8; nt++) {
                int lj = warpN * 64 + nt * 8 + c2;
                int gj = bn + lj;
                float v0 = acc[mt][nt][half * 2 + 0];
                float v1 = acc[mt][nt][half * 2 + 1];
                v0 = (gj <= gi) ? (v0 * 0.125f - (float)(gi - gj) * slope) : 0.f;
                v1 = (gj + 1 <= gi) ? (v1 * 0.125f - (float)(gi - gj - 1) * slope) : 0.f;
                float2 o; o.x = v0; o.y = v1;
                *(float2*)(out + (size_t)li * S + lj) = o;
            }
        }
    }
}

// -------------------- in-place causal row softmax (vectorized) -------------
__global__ __launch_bounds__(256)
void softmax_kernel(float* __restrict__ SA) {
    int row = blockIdx.x;           // h*S + i
    int i = row & (S - 1);
    float* p = SA + (size_t)row * S;
    int t = threadIdx.x;
    __shared__ float red[8];

    float v[8];
    float mx = -1e30f;
#pragma unroll
    for (int r = 0; r < 2; r++) {
        int j = r * 1024 + t * 4;
        float4 x4 = *(const float4*)(p + j);
        float xv[4] = {x4.x, x4.y, x4.z, x4.w};
#pragma unroll
        for (int q = 0; q < 4; q++) {
            float x = (j + q <= i) ? xv[q] : -1e30f;
            v[r * 4 + q] = x;
            mx = fmaxf(mx, x);
        }
    }
#pragma unroll
    for (int o = 16; o > 0; o >>= 1) mx = fmaxf(mx, __shfl_xor_sync(0xffffffffu, mx, o));
    if ((t & 31) == 0) red[t >> 5] = mx;
    __syncthreads();
    float bm = red[0];
#pragma unroll
    for (int w = 1; w < 8; w++) bm = fmaxf(bm, red[w]);
    __syncthreads();

    float sum = 0.f;
#pragma unroll
    for (int r = 0; r < 8; r++) {
        float e = __expf(v[r] - bm);
        v[r] = e;
        sum += e;
    }
#pragma unroll
    for (int o = 16; o > 0; o >>= 1) sum += __shfl_xor_sync(0xffffffffu, sum, o);
    if ((t & 31) == 0) red[t >> 5] = sum;
    __syncthreads();
    float bs = 0.f;
#pragma unroll
    for (int w = 0; w < 8; w++) bs += red[w];
    float inv = 1.f / bs;
#pragma unroll
    for (int r = 0; r < 2; r++) {
        int j = r * 1024 + t * 4;
        if (j + 3 <= i) {
            float4 o;
            o.x = v[r * 4 + 0] * inv; o.y = v[r * 4 + 1] * inv;
            o.z = v[r * 4 + 2] * inv; o.w = v[r * 4 + 3] * inv;
            *(float4*)(p + j) = o;
        } else {
#pragma unroll
            for (int q = 0; q < 4; q++)
                if (j + q <= i) p[j + q] = v[r * 4 + q] * inv;
        }
    }
}

// -------------------- z = SA @ V (tensor cores, tf32; Z written rounded) ---
__global__ __launch_bounds__(256)
void av_tc_kernel(const float* __restrict__ SA, const float* __restrict__ QKV,
                  float* __restrict__ Z) {
    const int LDS_ = 20;
    int bi = blockIdx.x, h = blockIdx.y;
    int bm = bi * 128;
    int tid = threadIdx.x;
    int lane = tid & 31, warp = tid >> 5;

    __shared__ float SAs[128 * LDS_];
    __shared__ float Vs[64 * LDS_];

    float acc[8][4];
#pragma unroll
    for (int j = 0; j < 8; j++)
#pragma unroll
        for (int r = 0; r < 4; r++) acc[j][r] = 0.f;

    int a_row = warp * 16 + (lane & 15);
    int a_col = (lane >> 4) * 4;
    int b_row = (lane & 7) + ((lane >> 4) << 3);
    int b_col = ((lane >> 3) & 1) * 4;

    const float* SAb = SA + ((size_t)h * S + bm) * S;
    const float* Vb = QKV + 2 * D + (size_t)h * 64;

    int nchunks = (bm + 128) / 16;
    for (int kc = 0; kc < nchunks; kc++) {
        int k0 = kc * 16;
#pragma unroll
        for (int i = 0; i < 2; i++) {
            int id = tid + i * 256;
            int row = id >> 2, c4 = (id & 3) * 4;
            float4 a = *(const float4*)(SAb + (size_t)row * S + k0 + c4);
            *(float4*)&SAs[row * LDS_ + c4] = cvt4(a);
        }
        {
            int jloc = tid >> 6, v = tid & 63;
#pragma unroll
            for (int i = 0; i < 4; i++) {
                int jj = jloc + i * 4;
                float x = Vb[(size_t)(k0 + jj) * (3 * D) + v];
                Vs[v * LDS_ + jj] = f2tf32f(x);
            }
        }
        __syncthreads();

#pragma unroll
        for (int ks = 0; ks < 2; ks++) {
            unsigned af[4];
            unsigned bf[8][2];
            ldsm_x4(af[0], af[1], af[2], af[3],
                    &SAs[a_row * LDS_ + ks * 8 + a_col]);
#pragma unroll
            for (int np = 0; np < 4; np++) {
                ldsm_x4(bf[2 * np][0], bf[2 * np][1], bf[2 * np + 1][0], bf[2 * np + 1][1],
                        &Vs[(b_row + np * 16) * LDS_ + ks * 8 + b_col]);
            }
#pragma unroll
            for (int nt = 0; nt < 8; nt++)
                mma_tf32(acc[nt], af, bf[nt]);
        }
        __syncthreads();
    }

    int g = lane >> 2, c2 = (lane & 3) * 2;
#pragma unroll
    for (int half = 0; half < 2; half++) {
        int m = bm + warp * 16 + g + half * 8;
#pragma unroll
        for (int nt = 0; nt < 8; nt++) {
            int n = h * 64 + nt * 8 + c2;
            float2 o;
            o.x = f2tf32f(acc[nt][half * 2 + 0]);   // Z feeds only the WO GEMM
            o.y = f2tf32f(acc[nt][half * 2 + 1]);
            *(float2*)(Z + (size_t)m * D + n) = o;
        }
    }
}

// --------------------------- launch ---------------------------------------
extern "C" void kernel_launch(void* const* d_in, const int* in_sizes, int n_in,
                              void* d_out, int out_size) {
    const float* X    = (const float*)d_in[0];
    const float* WQ   = (const float*)d_in[1];
    const float* WK   = (const float*)d_in[2];
    const float* WV   = (const float*)d_in[3];
    const float* WOw  = (const float*)d_in[4];
    const float* WOb  = (const float*)d_in[5];
    const float* FF1w = (const float*)d_in[6];
    const float* FF1b = (const float*)d_in[7];
    const float* FF2w = (const float*)d_in[8];
    const float* FF2b = (const float*)d_in[9];

    float* SA  = (float*)d_out;
    float* OUT = (float*)d_out + SA_ELEMS;

    float *WqkvT, *QKV, *Z, *ATT, *ATTc, *H1, *Xc, *WOc, *FF1c, *FF2c;
    cudaGetSymbolAddress((void**)&WqkvT, g_WqkvT);
    cudaGetSymbolAddress((void**)&QKV, g_QKV);
    cudaGetSymbolAddress((void**)&Z, g_Z);
    cudaGetSymbolAddress((void**)&ATT, g_ATT);
    cudaGetSymbolAddress((void**)&ATTc, g_ATTc);
    cudaGetSymbolAddress((void**)&H1, g_H1);
    cudaGetSymbolAddress((void**)&Xc, g_Xc);
    cudaGetSymbolAddress((void**)&WOc, g_WOc);
    cudaGetSymbolAddress((void**)&FF1c, g_FF1c);
    cudaGetSymbolAddress((void**)&FF2c, g_FF2c);

    // 0. pre-round all GEMM operands to tf32 (rna) once
    pack_w_kernel<<<(3 * D * D + 255) / 256, 256>>>(WQ, WK, WV);
    cvt_kernel<<<(S * D / 4 + 255) / 256, 256>>>(X, Xc, S * D / 4);
    cvt_kernel<<<(D * D / 4 + 255) / 256, 256>>>(WOw, WOc, D * D / 4);
    cvt_kernel<<<(DFF * D / 4 + 255) / 256, 256>>>(FF1w, FF1c, DFF * D / 4);
    cvt_kernel<<<(D * DFF / 4 + 255) / 256, 256>>>(FF2w, FF2c, D * DFF / 4);

    // 1. QKV projection (cp.async pipelined tf32)
    tf32gemm_ca<0><<<dim3(3 * D / 128, S / 128), 256>>>(
        Xc, WqkvT, nullptr, nullptr, QKV, nullptr, S, 3 * D, D);

    // 2. scores (+ALiBi, causal) into SA region (3xTF32, fp32-exact)
    scores_tc_kernel<<<dim3(S / 128, S / 128, H), 256>>>(QKV, SA);

    // 3. in-place softmax over causal prefix of each row
    softmax_kernel<<<H * S, 256>>>(SA);

    // 4. z = SA @ V (tensor cores; writes tf32-rounded Z)
    av_tc_kernel<<<dim3(S / 128, H), 256>>>(SA, QKV, Z);

    // 5. attouts = X + Z @ WO_w^T ; writes fp32 ATT + rounded ATTc
    tf32gemm_ca<3><<<dim3(D / 128, S / 128), 256>>>(
        Z, WOc, WOb, X, ATT, ATTc, S, D, D);

    // 6. H1 = tf32(relu(ATTc @ FF1_w^T + FF1_b))
    tf32gemm_ca<2><<<dim3(DFF / 128, S / 128), 256>>>(
        ATTc, FF1c, FF1b, nullptr, H1, nullptr, S, DFF, D);

    // 7. out = ATT + H1 @ FF2_w^T + FF2_b
    tf32gemm_ca<1><<<dim3(D / 128, S / 128), 256>>>(
        H1, FF2c, FF2b, ATT, OUT, nullptr, S, D, DFF);
}